// round 7
// baseline (speedup 1.0000x reference)
#include <cuda_runtime.h>
#include <stdint.h>

#define B 8192
#define AM_THREADS 256
#define AM_GRID 512
#define GROUPS_PER_BLOCK 4
#define D 512

__device__ int      g_idx_p[B];
__device__ int      g_idx_n[B];
__device__ float    g_rowloss[B];
__device__ int      g_order[B];
__device__ uint32_t g_one = 1;   // opaque 1: forces IMAD (fma pipe)

// ---------------- compile-time threefry for key derivation ----------------
struct K2 { uint32_t a, b; };
constexpr uint32_t rotl_c(uint32_t x, int r) { return (x << r) | (x >> (32 - r)); }
constexpr K2 tf_c(uint32_t k0, uint32_t k1, uint32_t x0, uint32_t x1) {
    uint32_t ks2 = k0 ^ k1 ^ 0x1BD11BDAu;
    x0 += k0; x1 += k1;
    const int RA[4] = {13, 15, 26, 6};
    const int RB[4] = {17, 29, 16, 24};
    for (int i = 0; i < 4; i++) { x0 += x1; x1 = rotl_c(x1, RA[i]); x1 ^= x0; }
    x0 += k1;  x1 += ks2 + 1u;
    for (int i = 0; i < 4; i++) { x0 += x1; x1 = rotl_c(x1, RB[i]); x1 ^= x0; }
    x0 += ks2; x1 += k0 + 2u;
    for (int i = 0; i < 4; i++) { x0 += x1; x1 = rotl_c(x1, RA[i]); x1 ^= x0; }
    x0 += k0;  x1 += k1 + 3u;
    for (int i = 0; i < 4; i++) { x0 += x1; x1 = rotl_c(x1, RB[i]); x1 ^= x0; }
    x0 += k1;  x1 += ks2 + 4u;
    for (int i = 0; i < 4; i++) { x0 += x1; x1 = rotl_c(x1, RA[i]); x1 ^= x0; }
    x0 += ks2; x1 += k0 + 5u;
    return K2{x0, x1};
}

constexpr K2 KP = tf_c(0u, 42u, 0u, 0u);   // split(key(42))[0]
constexpr K2 KN = tf_c(0u, 42u, 0u, 1u);   // split(key(42))[1]

constexpr uint32_t KP0 = KP.a, KP1 = KP.b, KPS = KP0 ^ KP1 ^ 0x1BD11BDAu;
constexpr uint32_t KN0 = KN.a, KN1 = KN.b, KNS = KN0 ^ KN1 ^ 0x1BD11BDAu;

constexpr uint32_t PC0 = KP0,      PC1 = KP1,      PC2 = KPS + 1u, PC3 = KPS;
constexpr uint32_t PC4 = KP0 + 2u, PC5 = KP1 + 3u, PC6 = KPS + 4u, PC7 = KP0 + 5u;
constexpr uint32_t NC0 = KN0,      NC1 = KN1,      NC2 = KNS + 1u, NC3 = KNS;
constexpr uint32_t NC4 = KN0 + 2u, NC5 = KN1 + 3u, NC6 = KNS + 4u, NC7 = KN0 + 5u;

#define MADD(d, a, c) asm("mad.lo.u32 %0, %1, %2, %3;" : "=r"(d) : "r"(a), "r"(one), "r"(c))
#define MSEL(d, IMM, c) asm("mad.lo.u32 %0, %1, %2, %3;" : "=r"(d) : "r"(pos01), "n"((int)(IMM)), "r"(c))

// 4-chain interleaved threefry round pieces (chains a,b,c,d)
#define R4_ADD() { MADD(a0,a1,a0); MADD(b0,b1,b0); MADD(c0,c1,c0); MADD(d0,d1,d0); }
#define R4_ROT(ra) { \
    a1 = __funnelshift_l(a1,a1,(ra)); b1 = __funnelshift_l(b1,b1,(ra)); \
    c1 = __funnelshift_l(c1,c1,(ra)); d1 = __funnelshift_l(d1,d1,(ra)); \
    a1 ^= a0; b1 ^= b0; c1 ^= c0; d1 ^= d0; }
#define R4(ra) { R4_ADD() R4_ROT(ra) }
#define INJ4(p0, p1) { \
    MADD(a0,p0,a0); MADD(b0,p0,b0); MADD(c0,p0,c0); MADD(d0,p0,d0); \
    MADD(a1,p1,a1); MADD(b1,p1,b1); MADD(c1,p1,c1); MADD(d1,p1,d1); }

// scalar single-chain eval (per-column key select inside) for mixed groups
#define RND1(ra) { MADD(x0, x1, x0); x1 = __funnelshift_l(x1, x1, (ra)); x1 ^= x0; }
__device__ __forceinline__ uint32_t tf_eval1(
    uint32_t one, uint32_t pos01, uint32_t cnt,
    uint32_t n0, uint32_t n1, uint32_t n2, uint32_t n3,
    uint32_t n4, uint32_t n5, uint32_t n6, uint32_t n7)
{
    uint32_t sk0, sk1, s2, s3, s4, s5, s6, s7;
    MSEL(sk0, PC0 - NC0, n0); MSEL(sk1, PC1 - NC1, n1);
    MSEL(s2,  PC2 - NC2, n2); MSEL(s3,  PC3 - NC3, n3);
    MSEL(s4,  PC4 - NC4, n4); MSEL(s5,  PC5 - NC5, n5);
    MSEL(s6,  PC6 - NC6, n6); MSEL(s7,  PC7 - NC7, n7);
    uint32_t x0, x1;
    MADD(x1, sk1, cnt);
    MADD(x0, x1, sk0);
    x1 = __funnelshift_l(x1, x1, 13); x1 ^= x0;
    RND1(15) RND1(26) RND1(6)
    MADD(x0, sk1, x0); MADD(x1, s2, x1);
    RND1(17) RND1(29) RND1(16) RND1(24)
    MADD(x0, s3, x0);  MADD(x1, s4, x1);
    RND1(13) RND1(15) RND1(26) RND1(6)
    MADD(x0, sk0, x0); MADD(x1, s5, x1);
    RND1(17) RND1(29) RND1(16) RND1(24)
    MADD(x0, sk1, x0); MADD(x1, s6, x1);
    RND1(13) RND1(15) RND1(26) RND1(6)
    MADD(x0, s3, x0);  MADD(x1, s7, x1);
    return (x0 ^ x1) & 0xFFFFFE00u;
}

// ---------------- stable counting sort of rows by label (14 labels) --------
__global__ void __launch_bounds__(448) order_kernel(const int* __restrict__ labels) {
    __shared__ int counts[14];
    __shared__ int base[14];
    const int w = threadIdx.x >> 5;
    const int lane = threadIdx.x & 31;

    int cnt = 0;
    for (int i = lane; i < B; i += 32) cnt += (labels[i] == w) ? 1 : 0;
    for (int off = 16; off > 0; off >>= 1) cnt += __shfl_down_sync(0xFFFFFFFFu, cnt, off);
    if (lane == 0) counts[w] = cnt;
    __syncthreads();
    if (threadIdx.x == 0) {
        int acc = 0;
        for (int l = 0; l < 14; l++) { base[l] = acc; acc += counts[l]; }
    }
    __syncthreads();
    int pos = base[w];
    for (int i0 = 0; i0 < B; i0 += 32) {
        const int i = i0 + lane;
        const bool m = (labels[i] == w);
        const unsigned bal = __ballot_sync(0xFFFFFFFFu, m);
        if (m) {
            const int rank = __popc(bal & ((1u << lane) - 1u));
            g_order[pos + rank] = i;
        }
        pos += __popc(bal);
    }
}

// ---------------- argmax over gumbel-bit matrices -------------------------
__global__ void __launch_bounds__(AM_THREADS, 4) argmax_kernel(const int* __restrict__ labels) {
    __shared__ uint8_t slab[B];
    __shared__ unsigned long long sredp[4][AM_THREADS / 32];
    __shared__ unsigned long long sredn[4][AM_THREADS / 32];
    __shared__ int srows[4];

    const int tid = threadIdx.x;
    for (int i = tid; i < B; i += AM_THREADS) slab[i] = (uint8_t)labels[i];
    __syncthreads();

    const uint32_t one = g_one;
    const uint32_t n0 = NC0, n1 = NC1, n2 = NC2, n3 = NC3;
    const uint32_t n4 = NC4, n5 = NC5, n6 = NC6, n7 = NC7;

    for (int gi = 0; gi < GROUPS_PER_BLOCK; gi++) {
        const int g = blockIdx.x * GROUPS_PER_BLOCK + gi;
        if (tid < 4) srows[tid] = g_order[g * 4 + tid];
        __syncthreads();
        const int rA = srows[0], rB = srows[1], rC = srows[2], rD = srows[3];
        const uint32_t lA = slab[rA], lB = slab[rB], lC = slab[rC], lD = slab[rD];
        const bool uniform = (lA == lB) && (lA == lC) && (lA == lD);

        // per-chain packed accumulators: v[31:9] | kinv[8:4]
        uint32_t bpA = 0u, bnA = 0u, bpB = 0u, bnB = 0u;
        uint32_t bpC = 0u, bnC = 0u, bpD = 0u, bnD = 0u;

        uint32_t cntA = ((uint32_t)rA << 13) + (uint32_t)tid;
        uint32_t cntB = ((uint32_t)rB << 13) + (uint32_t)tid;
        uint32_t cntC = ((uint32_t)rC << 13) + (uint32_t)tid;
        uint32_t cntD = ((uint32_t)rD << 13) + (uint32_t)tid;

        if (uniform) {
            // all 4 rows share label -> shared pos flag and shared subkeys
            const uint32_t myl = lA;
            uint32_t pb = 0u;
            #pragma unroll 8
            for (int k = 0; k < 32; k++)
                pb |= (uint32_t)(slab[tid + k * AM_THREADS] == myl) << k;

            uint32_t kinv = 31u << 4;
            #pragma unroll 2
            for (int k = 0; k < 32; k++) {
                const uint32_t pos01 = pb & 1u;

                uint32_t sk0, sk1, s2, s3, s4, s5, s6, s7;
                MSEL(sk0, PC0 - NC0, n0); MSEL(sk1, PC1 - NC1, n1);
                MSEL(s2,  PC2 - NC2, n2); MSEL(s3,  PC3 - NC3, n3);
                MSEL(s4,  PC4 - NC4, n4); MSEL(s5,  PC5 - NC5, n5);
                MSEL(s6,  PC6 - NC6, n6); MSEL(s7,  PC7 - NC7, n7);

                uint32_t a0, a1, b0, b1, c0, c1, d0, d1;
                MADD(a1, sk1, cntA); MADD(b1, sk1, cntB);
                MADD(c1, sk1, cntC); MADD(d1, sk1, cntD);
                MADD(a0, a1, sk0); MADD(b0, b1, sk0);
                MADD(c0, c1, sk0); MADD(d0, d1, sk0);
                R4_ROT(13)
                R4(15) R4(26) R4(6)
                INJ4(sk1, s2)
                R4(17) R4(29) R4(16) R4(24)
                INJ4(s3, s4)
                R4(13) R4(15) R4(26) R4(6)
                INJ4(sk0, s5)
                R4(17) R4(29) R4(16) R4(24)
                INJ4(sk1, s6)
                R4(13) R4(15) R4(26) R4(6)
                INJ4(s3, s7)

                const uint32_t vA = (a0 ^ a1) & 0xFFFFFE00u;
                const uint32_t vB = (b0 ^ b1) & 0xFFFFFE00u;
                const uint32_t vC = (c0 ^ c1) & 0xFFFFFE00u;
                const uint32_t vD = (d0 ^ d1) & 0xFFFFFE00u;
                uint32_t pA, pB, pC, pD;
                MADD(pA, vA, kinv); MADD(pB, vB, kinv);
                MADD(pC, vC, kinv); MADD(pD, vD, kinv);

                if (pos01) {
                    bpA = max(bpA, pA); bpB = max(bpB, pB);
                    bpC = max(bpC, pC); bpD = max(bpD, pD);
                } else {
                    bnA = max(bnA, pA); bnB = max(bnB, pB);
                    bnC = max(bnC, pC); bnD = max(bnD, pD);
                }
                cntA += AM_THREADS; cntB += AM_THREADS;
                cntC += AM_THREADS; cntD += AM_THREADS;
                kinv -= 16u;
                pb >>= 1;
            }
        } else {
            // mixed labels: 4 interleaved chains with per-chain pos flags
            uint32_t pba = 0u, pbb = 0u, pbc = 0u, pbd = 0u;
            #pragma unroll 8
            for (int k = 0; k < 32; k++) {
                const uint32_t lab = slab[tid + k * AM_THREADS];
                pba |= (uint32_t)(lab == lA) << k;
                pbb |= (uint32_t)(lab == lB) << k;
                pbc |= (uint32_t)(lab == lC) << k;
                pbd |= (uint32_t)(lab == lD) << k;
            }
            uint32_t kinv = 31u << 4;
            #pragma unroll 1
            for (int k = 0; k < 32; k++) {
                const uint32_t pa_ = pba & 1u, pb_ = pbb & 1u;
                const uint32_t pc_ = pbc & 1u, pd_ = pbd & 1u;
                const uint32_t vA = tf_eval1(one, pa_, cntA, n0,n1,n2,n3,n4,n5,n6,n7);
                const uint32_t vB = tf_eval1(one, pb_, cntB, n0,n1,n2,n3,n4,n5,n6,n7);
                const uint32_t vC = tf_eval1(one, pc_, cntC, n0,n1,n2,n3,n4,n5,n6,n7);
                const uint32_t vD = tf_eval1(one, pd_, cntD, n0,n1,n2,n3,n4,n5,n6,n7);
                uint32_t pA, pB, pC, pD;
                MADD(pA, vA, kinv); MADD(pB, vB, kinv);
                MADD(pC, vC, kinv); MADD(pD, vD, kinv);
                if (pa_) bpA = max(bpA, pA); else bnA = max(bnA, pA);
                if (pb_) bpB = max(bpB, pB); else bnB = max(bnB, pB);
                if (pc_) bpC = max(bpC, pC); else bnC = max(bnC, pC);
                if (pd_) bpD = max(bpD, pD); else bnD = max(bnD, pD);
                cntA += AM_THREADS; cntB += AM_THREADS;
                cntC += AM_THREADS; cntD += AM_THREADS;
                kinv -= 16u;
                pba >>= 1; pbb >>= 1; pbc >>= 1; pbd >>= 1;
            }
        }

        // merge: decode packed -> u64 (v23<<13)|(8191-col), warp reduce, store
        const uint32_t tu = (uint32_t)tid;
        const uint32_t accp[4] = {bpA, bpB, bpC, bpD};
        const uint32_t accn[4] = {bnA, bnB, bnC, bnD};
        const int w = tid >> 5;
        #pragma unroll
        for (int rr = 0; rr < 4; rr++) {
            const uint32_t kp_ = 31u - ((accp[rr] >> 4) & 31u);
            const uint32_t kn_ = 31u - ((accn[rr] >> 4) & 31u);
            const uint32_t colp = tu + kp_ * AM_THREADS;
            const uint32_t coln = tu + kn_ * AM_THREADS;
            unsigned long long pkp =
                ((unsigned long long)(accp[rr] >> 9) << 13) | (unsigned long long)(8191u - colp);
            unsigned long long pkn =
                ((unsigned long long)(accn[rr] >> 9) << 13) | (unsigned long long)(8191u - coln);
            for (int off = 16; off > 0; off >>= 1) {
                unsigned long long o;
                o = __shfl_down_sync(0xFFFFFFFFu, pkp, off); if (o > pkp) pkp = o;
                o = __shfl_down_sync(0xFFFFFFFFu, pkn, off); if (o > pkn) pkn = o;
            }
            if ((tid & 31) == 0) { sredp[rr][w] = pkp; sredn[rr][w] = pkn; }
        }
        __syncthreads();
        if (tid < 4) {
            const int rr = tid;
            unsigned long long mp = sredp[rr][0], mn = sredn[rr][0];
            #pragma unroll
            for (int i = 1; i < AM_THREADS / 32; i++) {
                if (sredp[rr][i] > mp) mp = sredp[rr][i];
                if (sredn[rr][i] > mn) mn = sredn[rr][i];
            }
            g_idx_p[srows[rr]] = 8191 - (int)(mp & 0x1FFFull);
            g_idx_n[srows[rr]] = 8191 - (int)(mn & 0x1FFFull);
        }
        __syncthreads();   // protect srows/sred before next group
    }
}

// Per-row hinge: cos(a,p) - cos(a,n) + margin, clamped at 0.
__global__ void __launch_bounds__(128) loss_kernel(const float* __restrict__ pred) {
    __shared__ float sred[5][4];
    const int r = blockIdx.x;
    const int tid = threadIdx.x;
    const int ip  = g_idx_p[r];
    const int in_ = g_idx_n[r];
    const float* __restrict__ a = pred + (size_t)r   * D;
    const float* __restrict__ p = pred + (size_t)ip  * D;
    const float* __restrict__ n = pred + (size_t)in_ * D;

    float saa = 0.f, spp = 0.f, snn = 0.f, sap = 0.f, san = 0.f;
    for (int j = tid; j < D; j += 128) {
        const float av = a[j], pv = p[j], nv = n[j];
        saa += av * av; spp += pv * pv; snn += nv * nv;
        sap += av * pv; san += av * nv;
    }
    for (int off = 16; off > 0; off >>= 1) {
        saa += __shfl_down_sync(0xFFFFFFFFu, saa, off);
        spp += __shfl_down_sync(0xFFFFFFFFu, spp, off);
        snn += __shfl_down_sync(0xFFFFFFFFu, snn, off);
        sap += __shfl_down_sync(0xFFFFFFFFu, sap, off);
        san += __shfl_down_sync(0xFFFFFFFFu, san, off);
    }
    const int w = tid >> 5;
    if ((tid & 31) == 0) {
        sred[0][w] = saa; sred[1][w] = spp; sred[2][w] = snn;
        sred[3][w] = sap; sred[4][w] = san;
    }
    __syncthreads();
    if (tid == 0) {
        float t0 = 0, t1 = 0, t2 = 0, t3 = 0, t4 = 0;
        #pragma unroll
        for (int i = 0; i < 4; i++) {
            t0 += sred[0][i]; t1 += sred[1][i]; t2 += sred[2][i];
            t3 += sred[3][i]; t4 += sred[4][i];
        }
        const float na = fmaxf(sqrtf(t0), 1e-6f);
        const float np = fmaxf(sqrtf(t1), 1e-6f);
        const float nn = fmaxf(sqrtf(t2), 1e-6f);
        g_rowloss[r] = fmaxf(t3 / (na * np) - t4 / (na * nn) + 0.1f, 0.0f);
    }
}

__global__ void __launch_bounds__(1024) reduce_kernel(float* __restrict__ out) {
    __shared__ float s[1024];
    const int tid = threadIdx.x;
    const float4* rl = (const float4*)g_rowloss;
    float4 v0 = rl[tid];
    float4 v1 = rl[tid + 1024];
    s[tid] = (v0.x + v0.y) + (v0.z + v0.w) + (v1.x + v1.y) + (v1.z + v1.w);
    __syncthreads();
    for (int st = 512; st > 0; st >>= 1) {
        if (tid < st) s[tid] += s[tid + st];
        __syncthreads();
    }
    if (tid == 0) out[0] = s[0] * (1.0f / (float)B);
}

extern "C" void kernel_launch(void* const* d_in, const int* in_sizes, int n_in,
                              void* d_out, int out_size) {
    const float* pred   = (const float*)d_in[0];
    const int*   labels = (const int*)d_in[1];
    float* out = (float*)d_out;

    order_kernel<<<1, 448>>>(labels);
    argmax_kernel<<<AM_GRID, AM_THREADS>>>(labels);
    loss_kernel<<<B, 128>>>(pred);
    reduce_kernel<<<1, 1024>>>(out);
}

// round 8
// speedup vs baseline: 1.0172x; 1.0172x over previous
#include <cuda_runtime.h>
#include <stdint.h>

#define B 8192
#define D 512
#define ROWS_PER_BLOCK 4
#define AM_THREADS 256

__device__ int      g_idx_p[B];
__device__ int      g_idx_n[B];
__device__ float    g_rowloss[B];
__device__ uint32_t g_one = 1;   // opaque 1: keeps selected adds as IMAD (fma-side pipe)

// ---------------- compile-time threefry for key derivation ----------------
struct K2 { uint32_t a, b; };
constexpr uint32_t rotl_c(uint32_t x, int r) { return (x << r) | (x >> (32 - r)); }
constexpr K2 tf_c(uint32_t k0, uint32_t k1, uint32_t x0, uint32_t x1) {
    uint32_t ks2 = k0 ^ k1 ^ 0x1BD11BDAu;
    x0 += k0; x1 += k1;
    const int RA[4] = {13, 15, 26, 6};
    const int RB[4] = {17, 29, 16, 24};
    for (int i = 0; i < 4; i++) { x0 += x1; x1 = rotl_c(x1, RA[i]); x1 ^= x0; }
    x0 += k1;  x1 += ks2 + 1u;
    for (int i = 0; i < 4; i++) { x0 += x1; x1 = rotl_c(x1, RB[i]); x1 ^= x0; }
    x0 += ks2; x1 += k0 + 2u;
    for (int i = 0; i < 4; i++) { x0 += x1; x1 = rotl_c(x1, RA[i]); x1 ^= x0; }
    x0 += k0;  x1 += k1 + 3u;
    for (int i = 0; i < 4; i++) { x0 += x1; x1 = rotl_c(x1, RB[i]); x1 ^= x0; }
    x0 += k1;  x1 += ks2 + 4u;
    for (int i = 0; i < 4; i++) { x0 += x1; x1 = rotl_c(x1, RA[i]); x1 ^= x0; }
    x0 += ks2; x1 += k0 + 5u;
    return K2{x0, x1};
}

constexpr K2 KP = tf_c(0u, 42u, 0u, 0u);   // split(key(42))[0]
constexpr K2 KN = tf_c(0u, 42u, 0u, 1u);   // split(key(42))[1]
constexpr uint32_t KP0 = KP.a, KP1 = KP.b, KPS = KP0 ^ KP1 ^ 0x1BD11BDAu;
constexpr uint32_t KN0 = KN.a, KN1 = KN.b, KNS = KN0 ^ KN1 ^ 0x1BD11BDAu;

// d = a*one + c  (IMAD; 'one' is an opaque runtime 1)
#define MADD(d, a, c) asm("mad.lo.u32 %0, %1, %2, %3;" : "=r"(d) : "r"(a), "r"(one), "r"(c))
// round with the x0+=x1 add on IMAD; rotate+xor stay on alu
#define RNDM(ra) { MADD(x0, x1, x0); x1 = __funnelshift_l(x1, x1, (ra)); x1 ^= x0; }

__global__ void __launch_bounds__(AM_THREADS) argmax_kernel(const int* __restrict__ labels) {
    __shared__ uint8_t slab[B];             // 8 KB
    __shared__ unsigned long long sredp[AM_THREADS / 32];
    __shared__ unsigned long long sredn[AM_THREADS / 32];

    const int tid = threadIdx.x;
    for (int i = tid; i < B; i += AM_THREADS) slab[i] = (uint8_t)labels[i];
    __syncthreads();

    const uint32_t one = g_one;
    const int r0 = blockIdx.x * ROWS_PER_BLOCK;

    for (int rr = 0; rr < ROWS_PER_BLOCK; rr++) {
        const int r = r0 + rr;
        const uint32_t myl = slab[r];

        uint32_t bp = 0u, bn = 0u;          // packed: v[31:9] | kinv[8:4]
        uint32_t cnt = ((uint32_t)r << 13) + (uint32_t)tid;
        uint32_t kinv = 31u << 4;

        #pragma unroll 4
        for (int k = 0; k < 32; k++) {
            const uint32_t lab = slab[tid + k * AM_THREADS];
            const bool pos = (lab == myl);
            const uint32_t k0  = pos ? KP0 : KN0;
            const uint32_t k1  = pos ? KP1 : KN1;
            const uint32_t ks2 = pos ? KPS : KNS;

            uint32_t x1 = cnt + k1;                         // IADD3
            uint32_t x0 = x1 + k0;                          // round-1 add folded (IADD3)
            x1 = __funnelshift_l(x1, x1, 13); x1 ^= x0;     // round 1 rot/xor
            RNDM(15) RNDM(26) RNDM(6)
            MADD(x0, k1, x0);  x1 = x1 + ks2 + 1u;          // inj1 (x1 via 3-input IADD3)
            RNDM(17) RNDM(29) RNDM(16) RNDM(24)
            MADD(x0, ks2, x0); x1 = x1 + k0 + 2u;           // inj2
            RNDM(13) RNDM(15) RNDM(26) RNDM(6)
            MADD(x0, k0, x0);  x1 = x1 + k1 + 3u;           // inj3
            RNDM(17) RNDM(29) RNDM(16) RNDM(24)
            MADD(x0, k1, x0);  x1 = x1 + ks2 + 4u;          // inj4
            RNDM(13) RNDM(15) RNDM(26) RNDM(6)
            MADD(x0, ks2, x0); x1 = x1 + k0 + 5u;           // inj5

            const uint32_t v = (x0 ^ x1) & 0xFFFFFE00u;     // fused xor+and (LOP3)
            uint32_t packed; MADD(packed, v, kinv);          // v | kinv (low bits free)
            if (pos) bp = max(bp, packed); else bn = max(bn, packed);

            cnt  += AM_THREADS;
            kinv -= 16u;
        }

        // decode packed -> u64 (v23<<13)|(8191-col); warp+block argmax (first-index ties)
        const uint32_t tu = (uint32_t)tid;
        const uint32_t kp_ = 31u - ((bp >> 4) & 31u);
        const uint32_t kn_ = 31u - ((bn >> 4) & 31u);
        const uint32_t colp = tu + kp_ * AM_THREADS;
        const uint32_t coln = tu + kn_ * AM_THREADS;
        unsigned long long pkp =
            ((unsigned long long)(bp >> 9) << 13) | (unsigned long long)(8191u - colp);
        unsigned long long pkn =
            ((unsigned long long)(bn >> 9) << 13) | (unsigned long long)(8191u - coln);

        for (int off = 16; off > 0; off >>= 1) {
            unsigned long long o;
            o = __shfl_down_sync(0xFFFFFFFFu, pkp, off); if (o > pkp) pkp = o;
            o = __shfl_down_sync(0xFFFFFFFFu, pkn, off); if (o > pkn) pkn = o;
        }
        const int w = tid >> 5;
        if ((tid & 31) == 0) { sredp[w] = pkp; sredn[w] = pkn; }
        __syncthreads();
        if (tid == 0) {
            unsigned long long mp = sredp[0], mn = sredn[0];
            #pragma unroll
            for (int i = 1; i < AM_THREADS / 32; i++) {
                if (sredp[i] > mp) mp = sredp[i];
                if (sredn[i] > mn) mn = sredn[i];
            }
            g_idx_p[r] = 8191 - (int)(mp & 0x1FFFull);
            g_idx_n[r] = 8191 - (int)(mn & 0x1FFFull);
        }
        __syncthreads();
    }
}

// Per-row hinge: cos(a,p) - cos(a,n) + margin, clamped at 0.
__global__ void __launch_bounds__(128) loss_kernel(const float* __restrict__ pred) {
    __shared__ float sred[5][4];
    const int r = blockIdx.x;
    const int tid = threadIdx.x;
    const int ip  = g_idx_p[r];
    const int in_ = g_idx_n[r];
    const float* __restrict__ a = pred + (size_t)r   * D;
    const float* __restrict__ p = pred + (size_t)ip  * D;
    const float* __restrict__ n = pred + (size_t)in_ * D;

    float saa = 0.f, spp = 0.f, snn = 0.f, sap = 0.f, san = 0.f;
    for (int j = tid; j < D; j += 128) {
        const float av = a[j], pv = p[j], nv = n[j];
        saa += av * av; spp += pv * pv; snn += nv * nv;
        sap += av * pv; san += av * nv;
    }
    for (int off = 16; off > 0; off >>= 1) {
        saa += __shfl_down_sync(0xFFFFFFFFu, saa, off);
        spp += __shfl_down_sync(0xFFFFFFFFu, spp, off);
        snn += __shfl_down_sync(0xFFFFFFFFu, snn, off);
        sap += __shfl_down_sync(0xFFFFFFFFu, sap, off);
        san += __shfl_down_sync(0xFFFFFFFFu, san, off);
    }
    const int w = tid >> 5;
    if ((tid & 31) == 0) {
        sred[0][w] = saa; sred[1][w] = spp; sred[2][w] = snn;
        sred[3][w] = sap; sred[4][w] = san;
    }
    __syncthreads();
    if (tid == 0) {
        float t0 = 0, t1 = 0, t2 = 0, t3 = 0, t4 = 0;
        #pragma unroll
        for (int i = 0; i < 4; i++) {
            t0 += sred[0][i]; t1 += sred[1][i]; t2 += sred[2][i];
            t3 += sred[3][i]; t4 += sred[4][i];
        }
        const float na = fmaxf(sqrtf(t0), 1e-6f);
        const float np = fmaxf(sqrtf(t1), 1e-6f);
        const float nn = fmaxf(sqrtf(t2), 1e-6f);
        g_rowloss[r] = fmaxf(t3 / (na * np) - t4 / (na * nn) + 0.1f, 0.0f);
    }
}

__global__ void __launch_bounds__(1024) reduce_kernel(float* __restrict__ out) {
    __shared__ float s[1024];
    const int tid = threadIdx.x;
    const float4* rl = (const float4*)g_rowloss;
    float4 v0 = rl[tid];
    float4 v1 = rl[tid + 1024];
    s[tid] = (v0.x + v0.y) + (v0.z + v0.w) + (v1.x + v1.y) + (v1.z + v1.w);
    __syncthreads();
    for (int st = 512; st > 0; st >>= 1) {
        if (tid < st) s[tid] += s[tid + st];
        __syncthreads();
    }
    if (tid == 0) out[0] = s[0] * (1.0f / (float)B);
}

extern "C" void kernel_launch(void* const* d_in, const int* in_sizes, int n_in,
                              void* d_out, int out_size) {
    const float* pred   = (const float*)d_in[0];
    const int*   labels = (const int*)d_in[1];
    float* out = (float*)d_out;

    argmax_kernel<<<B / ROWS_PER_BLOCK, AM_THREADS>>>(labels);
    loss_kernel<<<B, 128>>>(pred);
    reduce_kernel<<<1, 1024>>>(out);
}